// round 2
// baseline (speedup 1.0000x reference)
#include <cuda_runtime.h>

#define E    4096
#define NVAR 1024
#define NCHK 512
#define EPS32 1.1920929e-07f

// ---------------- scratch (device globals: no allocation allowed) ----------
__device__ int g_cnt[E];
__device__ int g_peers[E * 7];

// ---------------- kernel Z: zero the peer counters -------------------------
__global__ void zero_cnt_kernel() {
    int i = blockIdx.x * blockDim.x + threadIdx.x;
    if (i < E) g_cnt[i] = 0;
}

// ---------------- kernel A: extract check-graph peers ----------------------
// w_odd_to_even is symmetric with zero diagonal; each row has exactly 7
// nonzeros (check degree 8). Scan only the upper triangle (j > row) and
// record both directions. Warp gwid handles rows gwid and E-1-gwid so every
// warp scans exactly E-1 elements (load balance).
__global__ void build_peers_kernel(const float* __restrict__ w) {
    int gwid = (blockIdx.x * blockDim.x + threadIdx.x) >> 5;   // 0..2047
    int lane = threadIdx.x & 31;
#pragma unroll
    for (int pass = 0; pass < 2; pass++) {
        int row = pass ? (E - 1 - gwid) : gwid;
        const float* r = w + (size_t)row * E;
#pragma unroll 4
        for (int j = row + 1 + lane; j < E; j += 32) {
            if (r[j] != 0.0f) {
                int p = atomicAdd(&g_cnt[row], 1);
                g_peers[row * 7 + p] = j;
                int q = atomicAdd(&g_cnt[j], 1);
                g_peers[j * 7 + q] = row;
            }
        }
    }
}

// ---------------- math helpers ---------------------------------------------
__device__ __forceinline__ float tanh_acc(float a) {
    // tanh(a) = 1 - 2/(exp(2a)+1); __expf is lg2/ex2-based, ~1e-7 rel err.
    return 1.0f - __fdividef(2.0f, __expf(2.0f * a) + 1.0f);
}

__device__ __forceinline__ float atanh2(float v) {
    // reference clamps: v>=1 -> 1-eps, v<=-1 -> -1+eps (asymmetric, exact copy)
    v = (v >= 1.0f) ? (1.0f - EPS32) : v;
    v = (v <= -1.0f) ? (-1.0f + EPS32) : v;
    return __logf(__fdividef(1.0f + v, 1.0f - v));   // 2*atanh(v)
}

__device__ __forceinline__ float zsub(float o) {
    // reference maps exact zeros (non-edges AND exact-zero messages) to 1.0
    return (o == 0.0f) ? 1.0f : o;
}

// ---------------- kernel B: full decode, one persistent block ---------------
__global__ __launch_bounds__(1024, 1)
void decode_kernel(const float* __restrict__ x, float* __restrict__ out) {
    __shared__ float sh_odd[E];    // odd messages, CHECK-sorted order
    __shared__ float sh_even[E];   // even messages, natural (edge) order
    int* sh_odd_i  = (int*)sh_odd;   // prologue alias: check-id at rep edge
    int* sh_even_i = (int*)sh_even;  // prologue alias: scan temp / edge_of_slot

    const int t = threadIdx.x;                 // 0..1023 : variable node id
    const float llr = x[t];                    // llr_part for all 4 edges of var t

    // ---- prologue: derive deterministic check ids / slots from peer lists --
    int rep[4], rank[4];
    int nrep_local = 0;
#pragma unroll
    for (int i = 0; i < 4; i++) {
        int e = 4 * t + i;
        int mn = e, rk = 0;
#pragma unroll
        for (int k = 0; k < 7; k++) {
            int p = g_peers[e * 7 + k];
            mn = min(mn, p);
            rk += (p < e);                      // order-invariant rank
        }
        rep[i]  = mn;                           // min edge of the check = representative
        rank[i] = rk;                           // slot within check (edge-id order)
        nrep_local += (mn == e);
    }

    // block-wide inclusive scan of per-thread rep counts (deterministic ids)
    sh_even_i[t] = nrep_local;
    __syncthreads();
    for (int off = 1; off < 1024; off <<= 1) {
        int u = (t >= off) ? sh_even_i[t - off] : 0;
        __syncthreads();
        sh_even_i[t] += u;
        __syncthreads();
    }
    int cid = sh_even_i[t] - nrep_local;        // exclusive prefix
    __syncthreads();

    // publish check id at each rep edge position
#pragma unroll
    for (int i = 0; i < 4; i++) {
        int e = 4 * t + i;
        if (rep[i] == e) sh_odd_i[e] = cid++;
    }
    __syncthreads();

    int slot[4];
#pragma unroll
    for (int i = 0; i < 4; i++)
        slot[i] = sh_odd_i[rep[i]] * 8 + rank[i];   // check-sorted position
    __syncthreads();

    // inverse permutation: slot -> edge
#pragma unroll
    for (int i = 0; i < 4; i++) sh_even_i[slot[i]] = 4 * t + i;
    __syncthreads();
    int edst[4];
#pragma unroll
    for (int i = 0; i < 4; i++) edst[i] = sh_even_i[4 * t + i];
    __syncthreads();

    // even messages start at zero (layer-1 odd = tanh(0.5*llr) falls out)
    ((float4*)sh_even)[t] = make_float4(0.f, 0.f, 0.f, 0.f);
    __syncthreads();

    // ---- 5 BP iterations ----------------------------------------------------
#pragma unroll 1
    for (int it = 0; it < 5; it++) {
        // odd stage (natural order; this thread owns var t = edges 4t..4t+3)
        float4 ev = ((float4*)sh_even)[t];
        float vs = ev.x + ev.y + ev.z + ev.w;
        float o0 = tanh_acc(0.5f * (llr + vs - ev.x));
        float o1 = tanh_acc(0.5f * (llr + vs - ev.y));
        float o2 = tanh_acc(0.5f * (llr + vs - ev.z));
        float o3 = tanh_acc(0.5f * (llr + vs - ev.w));
        sh_odd[slot[0]] = o0;
        sh_odd[slot[1]] = o1;
        sh_odd[slot[2]] = o2;
        sh_odd[slot[3]] = o3;
        __syncthreads();

        // even stage (check-sorted; thread t owns slots 4t..4t+3 = half of check t>>1)
        const float4* bp = (const float4*)(sh_odd + 8 * (t >> 1));
        float4 lo = bp[0];
        float4 hi = bp[1];
        float a0 = zsub(lo.x), a1 = zsub(lo.y), a2 = zsub(lo.z), a3 = zsub(lo.w);
        float a4 = zsub(hi.x), a5 = zsub(hi.y), a6 = zsub(hi.z), a7 = zsub(hi.w);
        float q0, q1, q2, q3, om;
        if (t & 1) { q0 = a4; q1 = a5; q2 = a6; q3 = a7; om = a0 * a1 * a2 * a3; }
        else       { q0 = a0; q1 = a1; q2 = a2; q3 = a3; om = a4 * a5 * a6 * a7; }
        float p01 = q0 * q1, p23 = q2 * q3;
        float v0 = q1 * p23 * om;
        float v1 = q0 * p23 * om;
        float v2 = p01 * q3 * om;
        float v3 = p01 * q2 * om;
        sh_even[edst[0]] = atanh2(v0);
        sh_even[edst[1]] = atanh2(v1);
        sh_even[edst[2]] = atanh2(v2);
        sh_even[edst[3]] = atanh2(v3);
        __syncthreads();
    }

    // ---- epilogue: out[n] = sigmoid(x[n] + sum of even over var n) ----------
    float4 ev = ((float4*)sh_even)[t];
    float z = llr + ev.x + ev.y + ev.z + ev.w;
    out[t] = __fdividef(1.0f, 1.0f + __expf(-z));
}

// ---------------- launch ----------------------------------------------------
extern "C" void kernel_launch(void* const* d_in, const int* in_sizes, int n_in,
                              void* d_out, int out_size) {
    (void)in_sizes; (void)n_in; (void)out_size;
    const float* x            = (const float*)d_in[0];
    const float* w_odd_to_even = (const float*)d_in[2];
    float* out = (float*)d_out;

    zero_cnt_kernel<<<16, 256>>>();
    build_peers_kernel<<<256, 256>>>(w_odd_to_even);   // 2048 warps, rows paired
    decode_kernel<<<1, 1024>>>(x, out);
}

// round 3
// speedup vs baseline: 1.8733x; 1.8733x over previous
#include <cuda_runtime.h>

#define E    4096
#define NVAR 1024
#define NCHK 512
#define EPS32 1.1920929e-07f

// peers of each edge within its check, sorted ascending (7 per edge)
__device__ int g_peers[E * 7];

// ---------------- kernel A: extract check-graph peers (no atomics) ---------
// w_odd_to_even is symmetric, zero diagonal, exactly 7 nonzeros per row.
// One warp per row; float4 loads; warp-ballot compaction writes the 7 peer
// column indices in ascending order. No counters, no zeroing, no atomics.
__global__ void build_peers_kernel(const float4* __restrict__ w) {
    int row  = (blockIdx.x * blockDim.x + threadIdx.x) >> 5;   // 0..4095
    int lane = threadIdx.x & 31;
    const float4* r = w + (size_t)row * (E / 4);
    int* dst = g_peers + row * 7;
    int base = 0;
#pragma unroll 4
    for (int chunk = 0; chunk < 32; chunk++) {
        float4 v = r[chunk * 32 + lane];
        int c0 = (v.x != 0.0f), c1 = (v.y != 0.0f);
        int c2 = (v.z != 0.0f), c3 = (v.w != 0.0f);
        int cnt = c0 + c1 + c2 + c3;
        unsigned any = __ballot_sync(0xffffffffu, cnt != 0);
        if (any) {   // warp-uniform
            unsigned b0 = __ballot_sync(0xffffffffu, cnt & 1);
            unsigned b1 = __ballot_sync(0xffffffffu, cnt & 2);
            unsigned b2 = __ballot_sync(0xffffffffu, cnt & 4);
            unsigned mlt = (1u << lane) - 1u;
            int prior = base + __popc(b0 & mlt) + 2 * __popc(b1 & mlt)
                             + 4 * __popc(b2 & mlt);
            int col = chunk * 128 + lane * 4;
            if (c0) dst[prior++] = col;
            if (c1) dst[prior++] = col + 1;
            if (c2) dst[prior++] = col + 2;
            if (c3) dst[prior++] = col + 3;
            base += __popc(b0) + 2 * __popc(b1) + 4 * __popc(b2);
        }
    }
}

// ---------------- math helpers ---------------------------------------------
__device__ __forceinline__ float tanh_acc(float a) {
    // tanh(a) = 1 - 2/(exp(2a)+1); inf-safe (saturates to 1)
    return 1.0f - __fdividef(2.0f, __expf(2.0f * a) + 1.0f);
}

__device__ __forceinline__ float atanh2(float v) {
    // reference clamps: v>=1 -> 1-eps, v<=-1 -> -1+eps (exact copy)
    v = (v >= 1.0f) ? (1.0f - EPS32) : v;
    v = (v <= -1.0f) ? (-1.0f + EPS32) : v;
    return __logf(__fdividef(1.0f + v, 1.0f - v));   // 2*atanh(v)
}

__device__ __forceinline__ float zsub(float o) {
    // reference maps exact-zero messages to multiplicative identity
    return (o == 0.0f) ? 1.0f : o;
}

// ---------------- kernel B: full decode, one persistent block ---------------
// Natural edge order everywhere. Thread t owns variable t (edges 4t..4t+3);
// threads 0..511 additionally own one check each, whose 8 sorted edge ids
// live in registers for all 5 iterations.
__global__ __launch_bounds__(1024, 1)
void decode_kernel(const float* __restrict__ x, float* __restrict__ out) {
    __shared__ float sh_odd[E];      // odd messages, natural order
    __shared__ float sh_even[E];     // even messages, natural order
    __shared__ int   chk_list[NCHK]; // representative (min) edge of each check
    __shared__ int   chk_ctr;

    const int t = threadIdx.x;
    const float llr = x[t];

    if (t == 0) chk_ctr = 0;
    ((float4*)sh_even)[t] = make_float4(0.f, 0.f, 0.f, 0.f);
    __syncthreads();

    // claim checks: edge e is the representative iff e < its smallest peer
#pragma unroll
    for (int i = 0; i < 4; i++) {
        int e = 4 * t + i;
        if (e < g_peers[e * 7]) {
            int pos = atomicAdd(&chk_ctr, 1);   // assignment order is
            chk_list[pos] = e;                  // output-invariant
        }
    }
    __syncthreads();

    // check owners cache their sorted 8-edge list in registers
    int id0 = 0, id1 = 0, id2 = 0, id3 = 0, id4 = 0, id5 = 0, id6 = 0, id7 = 0;
    if (t < NCHK) {
        int rep = chk_list[t];
        id0 = rep;                      // rep is the minimum -> list is sorted
        id1 = g_peers[rep * 7 + 0];
        id2 = g_peers[rep * 7 + 1];
        id3 = g_peers[rep * 7 + 2];
        id4 = g_peers[rep * 7 + 3];
        id5 = g_peers[rep * 7 + 4];
        id6 = g_peers[rep * 7 + 5];
        id7 = g_peers[rep * 7 + 6];
    }

    // ---- 5 BP iterations ----------------------------------------------------
#pragma unroll 1
    for (int it = 0; it < 5; it++) {
        // odd stage: fully vectorized, natural order
        float4 ev = ((float4*)sh_even)[t];
        float vs = ev.x + ev.y + ev.z + ev.w;
        float4 od;
        od.x = tanh_acc(0.5f * (llr + vs - ev.x));
        od.y = tanh_acc(0.5f * (llr + vs - ev.y));
        od.z = tanh_acc(0.5f * (llr + vs - ev.z));
        od.w = tanh_acc(0.5f * (llr + vs - ev.w));
        ((float4*)sh_odd)[t] = od;
        __syncthreads();

        // even stage: 512 check owners, gather 8, extrinsic products, scatter 8
        if (t < NCHK) {
            float a0 = zsub(sh_odd[id0]), a1 = zsub(sh_odd[id1]);
            float a2 = zsub(sh_odd[id2]), a3 = zsub(sh_odd[id3]);
            float a4 = zsub(sh_odd[id4]), a5 = zsub(sh_odd[id5]);
            float a6 = zsub(sh_odd[id6]), a7 = zsub(sh_odd[id7]);
            float p01 = a0 * a1, p23 = a2 * a3, p45 = a4 * a5, p67 = a6 * a7;
            float q03 = p01 * p23, q47 = p45 * p67;
            sh_even[id0] = atanh2(a1 * p23 * q47);
            sh_even[id1] = atanh2(a0 * p23 * q47);
            sh_even[id2] = atanh2(p01 * a3 * q47);
            sh_even[id3] = atanh2(p01 * a2 * q47);
            sh_even[id4] = atanh2(q03 * a5 * p67);
            sh_even[id5] = atanh2(q03 * a4 * p67);
            sh_even[id6] = atanh2(q03 * p45 * a7);
            sh_even[id7] = atanh2(q03 * p45 * a6);
        }
        __syncthreads();
    }

    // ---- epilogue: out[n] = sigmoid(x[n] + sum of even over var n) ----------
    float4 ev = ((float4*)sh_even)[t];
    float z = llr + ev.x + ev.y + ev.z + ev.w;
    out[t] = __fdividef(1.0f, 1.0f + __expf(-z));
}

// ---------------- launch ----------------------------------------------------
extern "C" void kernel_launch(void* const* d_in, const int* in_sizes, int n_in,
                              void* d_out, int out_size) {
    (void)in_sizes; (void)n_in; (void)out_size;
    const float*  x = (const float*)d_in[0];
    const float4* w = (const float4*)d_in[2];   // w_odd_to_even [E,E]
    float* out = (float*)d_out;

    build_peers_kernel<<<512, 256>>>(w);   // one warp per row
    decode_kernel<<<1, 1024>>>(x, out);
}